// round 14
// baseline (speedup 1.0000x reference)
#include <cuda_runtime.h>
#include <cuda_bf16.h>
#include <cstdint>

// Problem constants
#define Bb 2048
#define Tt 2048
#define S  16  // SMEM ring steps (4 chunks x 4 steps); buffers padded by S steps
#define C  4   // steps per chunk / commit group
// F=8, U=3, 3U=9

#define LOG2E 1.4426950408889634f

// Scratch: __device__ globals (allocation-free rule). Padded by S steps so
// ALL pipeline loads are unconditional and in-bounds.
__device__ float4 g_bufZ[(size_t)(Tt + S) * Bb];  // {.5*xz0,.5*xz1,.5*xz2, .5*mask}
__device__ float4 g_bufR[(size_t)(Tt + S) * Bb];  // {-log2e*xr0..2, 0}
__device__ float4 g_bufH[(size_t)(Tt + S) * Bb];  // {2log2e*xh0..2, 0}
__device__ float  g_outT[(size_t)Tt * Bb];        // out in [t][b] layout

typedef unsigned long long u64;
typedef unsigned int u32;

// HW tanh: 1 op, but SLOW latency (~95cyc inferred R13) — off-critical-path only
__device__ __forceinline__ float tanh_fast(float x) {
    float y;
    asm("tanh.approx.f32 %0, %1;" : "=f"(y) : "f"(x));
    return y;
}
// MUFU.EX2 / MUFU.RCP: measured lat 16 — use these ON the critical path
__device__ __forceinline__ float ex2f(float x) {
    float y;
    asm("ex2.approx.f32 %0, %1;" : "=f"(y) : "f"(x));
    return y;
}
__device__ __forceinline__ float rcpf(float x) {
    float y;
    asm("rcp.approx.f32 %0, %1;" : "=f"(y) : "f"(x));
    return y;
}

// cp.async 16B: completion via commit-group counters
__device__ __forceinline__ void cp16(u32 smem_dst, const void* gsrc) {
    asm volatile("cp.async.cg.shared.global [%0], [%1], 16;"
                 :: "r"(smem_dst), "l"(gsrc) : "memory");
}
__device__ __forceinline__ void cp_commit() {
    asm volatile("cp.async.commit_group;" ::: "memory");
}
template <int N>
__device__ __forceinline__ void cp_wait() {
    asm volatile("cp.async.wait_group %0;" :: "n"(N) : "memory");
}

__device__ __forceinline__ u32 smem_u32(const void* p) {
    u32 a;
    asm("{ .reg .u64 t; cvta.to.shared.u64 t, %1; cvt.u32.u64 %0, t; }"
        : "=r"(a) : "l"(p));
    return a;
}

// ---------------------------------------------------------------------------
// Kernel A: input projection + mask -> [t][b]-major packed tiles.
// Pre-folds all activation argument scalings:
//   z:  0.5*a_z      (sigmoid-via-tanh needs a/2)       + mask as 0.5*m
//   r: -log2e*a_r    (sigmoid = rcp(1+ex2(-log2e*a)))
//   h:  2log2e*xh    (tanh(y) = 1-2*rcp(1+ex2(2log2e*y)))
// ---------------------------------------------------------------------------
__global__ void __launch_bounds__(256) prep_kernel(
    const float* __restrict__ x,       // [B][T][8]
    const float* __restrict__ kern,    // [8][9]
    const float* __restrict__ bias_i,  // [9]
    const float* __restrict__ bias_r)  // [9]
{
    const int b  = blockIdx.x * 256 + threadIdx.x;
    const int t0 = blockIdx.y * 8;

    float bs[9];
#pragma unroll
    for (int j = 0; j < 9; j++) bs[j] = __ldg(bias_i + j) + __ldg(bias_r + j);
    float wv[8][9];
#pragma unroll
    for (int f = 0; f < 8; f++)
#pragma unroll
        for (int j = 0; j < 9; j++) wv[f][j] = __ldg(kern + f * 9 + j);

    const float4* x4 = reinterpret_cast<const float4*>(x) + (size_t)b * (Tt * 2);

#pragma unroll
    for (int i = 0; i < 8; i++) {
        const int t = t0 + i;
        float4 a = __ldg(x4 + (size_t)t * 2);
        float4 c = __ldg(x4 + (size_t)t * 2 + 1);
        float xf[8] = {a.x, a.y, a.z, a.w, c.x, c.y, c.z, c.w};

        float m = 0.0f;
#pragma unroll
        for (int f = 0; f < 8; f++)
            if (xf[f] != 0.0f) m = 0.5f;   // store 0.5*mask

        float acc[9];
#pragma unroll
        for (int j = 0; j < 9; j++) {
            float s = bs[j];
#pragma unroll
            for (int f = 0; f < 8; f++) s = fmaf(xf[f], wv[f][j], s);
            acc[j] = s;
        }

        const size_t o = (size_t)t * Bb + b;
        g_bufZ[o] = make_float4(0.5f * acc[0], 0.5f * acc[1], 0.5f * acc[2], m);
        g_bufR[o] = make_float4(-LOG2E * acc[3], -LOG2E * acc[4], -LOG2E * acc[5], 0.0f);
        g_bufH[o] = make_float4(2.0f * LOG2E * acc[6], 2.0f * LOG2E * acc[7],
                                2.0f * LOG2E * acc[8], 0.0f);
    }
}

// ---------------------------------------------------------------------------
// Kernel B: sequential GRU scan, 64 blocks x 32 threads = 2048 lanes.
// Critical-path redesign: the serial h->h chain runs through r and hc.
//   r  = rcp(1 + ex2(a_r'))          (EX2/RCP: lat 16 each, measured)
//   hc = 1 - 2*rcp(1 + ex2(y'))      (args pre-scaled in prep / rk columns)
//   z  = 0.5+0.5*tanh(a_z/2)         (tanh.approx off the critical path)
// All gate FMAs scalar (issue slack proven by R13; removes pk/upk MOVs from
// the chain). cp.async SMEM ring, 4 chunks x 4 steps, one wait+commit per
// chunk (R12 discipline). No __syncthreads anywhere.
// ---------------------------------------------------------------------------
__global__ void __launch_bounds__(32) scan_kernel(
    const float* __restrict__ rk,       // [3][9]
    const float* __restrict__ dense_w,  // [3][1]
    const float* __restrict__ dense_b)  // [1]
{
    __shared__ float4 ring[S][3][32];   // 24 KB

    const int tid = threadIdx.x;
    const int b = blockIdx.x * 32 + tid;

    // column scaling matches prep's pre-activation scaling
    float K[3][9];
#pragma unroll
    for (int u = 0; u < 3; u++)
#pragma unroll
        for (int j = 0; j < 9; j++) {
            float v = __ldg(rk + u * 9 + j);
            K[u][j] = (j < 3) ? 0.5f * v
                    : (j < 6) ? -LOG2E * v
                              : 2.0f * LOG2E * v;
        }

    // dense_w pre-doubled: out = halfm * dot(h, 2w) + db == m*dot(h,w)+db
    const float w0 = 2.0f * __ldg(dense_w);
    const float w1 = 2.0f * __ldg(dense_w + 1);
    const float w2 = 2.0f * __ldg(dense_w + 2);
    const float db = __ldg(dense_b);

    float h0 = 0.0f, h1 = 0.0f, h2 = 0.0f;

    // smem lane addresses per stage
    u32 rz[S], rr[S], rh[S];
#pragma unroll
    for (int d = 0; d < S; d++) {
        rz[d] = smem_u32(&ring[d][0][tid]);
        rr[d] = smem_u32(&ring[d][1][tid]);
        rh[d] = smem_u32(&ring[d][2][tid]);
    }

    // prologue: 4 chunk-groups (steps 0..15), one commit per chunk
#pragma unroll
    for (int c = 0; c < S / C; c++) {
#pragma unroll
        for (int s = 0; s < C; s++) {
            const int st = c * C + s;
            const size_t o = (size_t)st * Bb + b;
            cp16(rz[st], &g_bufZ[o]);
            cp16(rr[st], &g_bufR[o]);
            cp16(rh[st], &g_bufH[o]);
        }
        cp_commit();
    }

    // chunk 0 resident: committed=4, need group0 -> pending<=3
    cp_wait<3>();
    float4 nz = ring[0][0][tid];
    float4 nr = ring[0][1][tid];
    float4 nh = ring[0][2][tid];

    for (int c = 0; c < Tt / C; c++) {
        const int base = c * C;
#pragma unroll
        for (int s = 0; s < C; s++) {
            const int tc = base + s;
            const int ns = (tc + 1) & (S - 1);   // next stage

            const float4 vz = nz;
            const float4 vr = nr;
            const float4 vh = nh;

            // Chunk boundary: ensure chunk c+1 resident.
            if (s == C - 1) cp_wait<2>();

            nz = *reinterpret_cast<float4*>((char*)ring + (ns * 3 + 0) * 512 + tid * 16);
            nr = *reinterpret_cast<float4*>((char*)ring + (ns * 3 + 1) * 512 + tid * 16);
            nh = *reinterpret_cast<float4*>((char*)ring + (ns * 3 + 2) * 512 + tid * 16);

            // Refill this chunk's slot with chunk c+4 (padded tail covers it).
            if (s == C - 1) {
                const int slot = c & 3;
#pragma unroll
                for (int q = 0; q < C; q++) {
                    const int st = slot * C + q;
                    const size_t o = (size_t)(base + S + q) * Bb + b;
                    cp16(rz[st], &g_bufZ[o]);
                    cp16(rr[st], &g_bufR[o]);
                    cp16(rh[st], &g_bufH[o]);
                }
                cp_commit();
            }

            // ---- GRU step: r & hc first (critical path), z in the slack ----
            // a_r' = -log2e * a_r  (folded); e^{-a_r} = ex2(a_r')
            const float ar0 = fmaf(h2, K[2][3], fmaf(h1, K[1][3], fmaf(h0, K[0][3], vr.x)));
            const float ar1 = fmaf(h2, K[2][4], fmaf(h1, K[1][4], fmaf(h0, K[0][4], vr.y)));
            const float ar2 = fmaf(h2, K[2][5], fmaf(h1, K[1][5], fmaf(h0, K[0][5], vr.z)));
            const float r0 = rcpf(1.0f + ex2f(ar0));
            const float r1 = rcpf(1.0f + ex2f(ar1));
            const float r2 = rcpf(1.0f + ex2f(ar2));

            // hh' = 2log2e * h@rk_h  (folded via K columns 6..8)
            const float hh0 = fmaf(h2, K[2][6], fmaf(h1, K[1][6], h0 * K[0][6]));
            const float hh1 = fmaf(h2, K[2][7], fmaf(h1, K[1][7], h0 * K[0][7]));
            const float hh2 = fmaf(h2, K[2][8], fmaf(h1, K[1][8], h0 * K[0][8]));

            // y' = 2log2e*(xh + r*hh); tanh(y) = 1 - 2*rcp(1 + ex2(y'))
            const float hc0 = fmaf(-2.0f, rcpf(1.0f + ex2f(fmaf(r0, hh0, vh.x))), 1.0f);
            const float hc1 = fmaf(-2.0f, rcpf(1.0f + ex2f(fmaf(r1, hh1, vh.y))), 1.0f);
            const float hc2 = fmaf(-2.0f, rcpf(1.0f + ex2f(fmaf(r2, hh2, vh.z))), 1.0f);

            // z-gate (off critical path): g = m*(1-z) = halfm*(1 - tanh(a_z/2))
            const float az0 = fmaf(h2, K[2][0], fmaf(h1, K[1][0], fmaf(h0, K[0][0], vz.x)));
            const float az1 = fmaf(h2, K[2][1], fmaf(h1, K[1][1], fmaf(h0, K[0][1], vz.y)));
            const float az2 = fmaf(h2, K[2][2], fmaf(h1, K[1][2], fmaf(h0, K[0][2], vz.z)));
            const float halfm = vz.w;  // 0.5*mask
            const float g0 = fmaf(-halfm, tanh_fast(az0), halfm);
            const float g1 = fmaf(-halfm, tanh_fast(az1), halfm);
            const float g2 = fmaf(-halfm, tanh_fast(az2), halfm);

            // h_new = h + g*(hc - h)
            h0 = fmaf(g0, hc0 - h0, h0);
            h1 = fmaf(g1, hc1 - h1, h1);
            h2 = fmaf(g2, hc2 - h2, h2);

            // out = halfm * dot(h_new, 2w) + db
            const float dot = fmaf(h2, w2, fmaf(h1, w1, h0 * w0));
            g_outT[(size_t)tc * Bb + b] = fmaf(halfm, dot, db);
        }
    }
}

// ---------------------------------------------------------------------------
// Kernel C: transpose g_outT[t][b] -> out[b][t]
// ---------------------------------------------------------------------------
__global__ void transpose_kernel(float* __restrict__ out) {
    __shared__ float tile[32][33];
    const int bBase = blockIdx.x * 32;
    const int tBase = blockIdx.y * 32;

    tile[threadIdx.y][threadIdx.x] =
        g_outT[(size_t)(tBase + threadIdx.y) * Bb + (bBase + threadIdx.x)];
    __syncthreads();
    out[(size_t)(bBase + threadIdx.y) * Tt + (tBase + threadIdx.x)] =
        tile[threadIdx.x][threadIdx.y];
}

// ---------------------------------------------------------------------------
extern "C" void kernel_launch(void* const* d_in, const int* in_sizes, int n_in,
                              void* d_out, int out_size) {
    const float* x       = (const float*)d_in[0];  // (B,T,8)
    const float* kern    = (const float*)d_in[1];  // (8,9)
    const float* rk      = (const float*)d_in[2];  // (3,9)
    const float* bias_i  = (const float*)d_in[3];  // (9,)
    const float* bias_r  = (const float*)d_in[4];  // (9,)
    const float* dense_w = (const float*)d_in[5];  // (3,1)
    const float* dense_b = (const float*)d_in[6];  // (1,)
    float* out = (float*)d_out;                    // (B,T,1)

    (void)in_sizes; (void)n_in; (void)out_size;

    dim3 gA(Bb / 256, Tt / 8);
    prep_kernel<<<gA, 256>>>(x, kern, bias_i, bias_r);

    scan_kernel<<<Bb / 32, 32>>>(rk, dense_w, dense_b);

    dim3 gC(Bb / 32, Tt / 32);
    transpose_kernel<<<gC, dim3(32, 32)>>>(out);
}

// round 15
// speedup vs baseline: 1.5974x; 1.5974x over previous
#include <cuda_runtime.h>
#include <cuda_bf16.h>
#include <cstdint>

// Problem constants
#define Bb 2048
#define Tt 2048
#define S  16  // SMEM ring steps (4 chunks x 4 steps)
#define C  4   // steps per chunk / commit group
// F=8, U=3, 3U=9

// Scratch (allocation-free rule): only the [t][b] output staging remains —
// prep is fused into the scan, so the 3x192MB gate buffers are GONE.
__device__ float g_outT[(size_t)Tt * Bb];

typedef unsigned long long u64;
typedef unsigned int u32;

// HW tanh (sm_75+)
__device__ __forceinline__ float tanh_fast(float x) {
    float y;
    asm("tanh.approx.f32 %0, %1;" : "=f"(y) : "f"(x));
    return y;
}

// f32x2 packed helpers (Blackwell FFMA2 — ptxas never auto-fuses from C++)
__device__ __forceinline__ u64 pk(float lo, float hi) {
    u64 r;
    asm("mov.b64 %0, {%1,%2};" : "=l"(r) : "f"(lo), "f"(hi));
    return r;
}
__device__ __forceinline__ void upk(u64 v, float& lo, float& hi) {
    asm("mov.b64 {%0,%1}, %2;" : "=f"(lo), "=f"(hi) : "l"(v));
}
__device__ __forceinline__ u64 fma2(u64 a, u64 b, u64 c) {
    u64 d;
    asm("fma.rn.f32x2 %0, %1, %2, %3;" : "=l"(d) : "l"(a), "l"(b), "l"(c));
    return d;
}

// cp.async 16B: completion via commit-group counters
__device__ __forceinline__ void cp16(u32 smem_dst, const void* gsrc) {
    asm volatile("cp.async.cg.shared.global [%0], [%1], 16;"
                 :: "r"(smem_dst), "l"(gsrc) : "memory");
}
__device__ __forceinline__ void cp_commit() {
    asm volatile("cp.async.commit_group;" ::: "memory");
}
template <int N>
__device__ __forceinline__ void cp_wait() {
    asm volatile("cp.async.wait_group %0;" :: "n"(N) : "memory");
}

__device__ __forceinline__ u32 smem_u32(const void* p) {
    u32 a;
    asm("{ .reg .u64 t; cvta.to.shared.u64 t, %1; cvt.u32.u64 %0, t; }"
        : "=r"(a) : "l"(p));
    return a;
}

// ---------------------------------------------------------------------------
// FUSED scan: 64 blocks x 32 threads = 2048 lanes, one batch row per lane.
// Streams x[b][t][0..7] (32B/step, per-lane contiguous) through a chunked
// cp.async SMEM ring (R12 discipline: one wait + one commit per 4-step chunk).
// Computes xw = x@kernel + biases inline with packed FFMA2 (off the h-chain;
// R13 proved the issue slack), then the R12 tanh gate math.
// ---------------------------------------------------------------------------
__global__ void __launch_bounds__(32) scan_kernel(
    const float* __restrict__ x,        // [B][T][8]
    const float* __restrict__ kern,     // [8][9]
    const float* __restrict__ rk,       // [3][9]
    const float* __restrict__ bias_i,   // [9]
    const float* __restrict__ bias_r,   // [9]
    const float* __restrict__ dense_w,  // [3][1]
    const float* __restrict__ dense_b)  // [1]
{
    __shared__ float4 ring[S][2][32];   // 16 KB: 2 float4 of x per lane/stage

    const int tid = threadIdx.x;
    const int b = blockIdx.x * 32 + tid;

    // ---- input-projection weights, column-scaled & packed ----
    // cols 0-5 (z,r gates) pre-scaled by 0.5 (sigmoid-via-tanh), cols 6-8 raw.
    float bsr[9];
#pragma unroll
    for (int j = 0; j < 9; j++) {
        float v = __ldg(bias_i + j) + __ldg(bias_r + j);
        bsr[j] = (j < 6) ? 0.5f * v : v;
    }
    u64 Wx[8][4];    // col pairs (0,1),(2,3),(4,5),(6,7)
    float Wx8[8];    // col 8
#pragma unroll
    for (int f = 0; f < 8; f++) {
#pragma unroll
        for (int p = 0; p < 4; p++) {
            float lo = __ldg(kern + f * 9 + 2 * p);
            float hi = __ldg(kern + f * 9 + 2 * p + 1);
            if (2 * p < 6)     lo *= 0.5f;
            if (2 * p + 1 < 6) hi *= 0.5f;
            Wx[f][p] = pk(lo, hi);
        }
        Wx8[f] = __ldg(kern + f * 9 + 8);
    }
    const u64 B01 = pk(bsr[0], bsr[1]);
    const u64 B23 = pk(bsr[2], bsr[3]);
    const u64 B45 = pk(bsr[4], bsr[5]);
    const u64 B67 = pk(bsr[6], bsr[7]);
    const float B8 = bsr[8];

    // ---- recurrent weights, z/r cols pre-halved (R12) ----
    float K[3][9];
#pragma unroll
    for (int u = 0; u < 3; u++)
#pragma unroll
        for (int j = 0; j < 9; j++) {
            float v = __ldg(rk + u * 9 + j);
            K[u][j] = (j < 6) ? 0.5f * v : v;
        }

    // dense_w pre-doubled: out = halfm*dot(h,2w)+db == m*dot(h,w)+db
    const float w0 = 2.0f * __ldg(dense_w);
    const float w1 = 2.0f * __ldg(dense_w + 1);
    const float w2 = 2.0f * __ldg(dense_w + 2);
    const float db = __ldg(dense_b);

    float h0 = 0.0f, h1 = 0.0f, h2 = 0.0f;

    const float* gx = x + (size_t)b * Tt * 8;   // this lane's row
    const u32 sbase = smem_u32(ring) + (tid << 4);
    char* const rbase = (char*)ring + (tid << 4);
    // addr(stage st, q) = sbase + ((st*2+q) << 9)

    // prologue: chunks 0..3 (steps 0..15), one commit per chunk
#pragma unroll
    for (int c = 0; c < S / C; c++) {
#pragma unroll
        for (int s = 0; s < C; s++) {
            const int st = c * C + s;
            cp16(sbase + ((u32)(st * 2) << 9),       gx + (size_t)st * 8);
            cp16(sbase + ((u32)(st * 2 + 1) << 9),   gx + (size_t)st * 8 + 4);
        }
        cp_commit();
    }

    // chunk 0 resident: committed=4, need group0 -> pending<=3
    cp_wait<3>();
    float4 nx0 = *reinterpret_cast<float4*>(rbase + (0 << 9));
    float4 nx1 = *reinterpret_cast<float4*>(rbase + (1 << 9));

    for (int c = 0; c < Tt / C; c++) {
        const int base_t = c * C;
#pragma unroll
        for (int s = 0; s < C; s++) {
            const int tc = base_t + s;
            const int ns = (tc + 1) & (S - 1);   // next stage

            const float4 a = nx0;
            const float4 d = nx1;

            // chunk boundary: ensure chunk c+1 resident
            // committed = 4+c, need group c+1 done -> pending <= 2
            if (s == C - 1) cp_wait<2>();

            nx0 = *reinterpret_cast<float4*>(rbase + (size_t)(ns * 2) * 512);
            nx1 = *reinterpret_cast<float4*>(rbase + (size_t)(ns * 2 + 1) * 512);

            // refill this chunk's slot with chunk c+4 (clamp t: x not padded)
            if (s == C - 1) {
                const int slot = c & 3;
#pragma unroll
                for (int q = 0; q < C; q++) {
                    const int st = slot * C + q;
                    int tp = base_t + S + q;
                    if (tp > Tt - 1) tp = Tt - 1;   // clamped, always in-bounds
                    cp16(sbase + ((u32)(st * 2) << 9),     gx + (size_t)tp * 8);
                    cp16(sbase + ((u32)(st * 2 + 1) << 9), gx + (size_t)tp * 8 + 4);
                }
                cp_commit();
            }

            const float xf[8] = {a.x, a.y, a.z, a.w, d.x, d.y, d.z, d.w};

            // mask: any(x != 0) -> halfm in {0, 0.5}
            float sabs = fabsf(xf[0]);
#pragma unroll
            for (int f = 1; f < 8; f++) sabs += fabsf(xf[f]);
            const float halfm = (sabs != 0.0f) ? 0.5f : 0.0f;

            // xw (packed, off the h-chain): pre-activation inputs
            u64 a01 = B01, a23 = B23, a45 = B45, a67 = B67;
            float a8 = B8;
#pragma unroll
            for (int f = 0; f < 8; f++) {
                const u64 xp = pk(xf[f], xf[f]);
                a01 = fma2(xp, Wx[f][0], a01);
                a23 = fma2(xp, Wx[f][1], a23);
                a45 = fma2(xp, Wx[f][2], a45);
                a67 = fma2(xp, Wx[f][3], a67);
                a8  = fmaf(xf[f], Wx8[f], a8);
            }
            float xz0, xz1, xz2, xr0, xr1, xr2, xh0, xh1;
            upk(a01, xz0, xz1);
            upk(a23, xz2, xr0);
            upk(a45, xr1, xr2);
            upk(a67, xh0, xh1);
            const float xh2 = a8;

            // ---- R12 gate math (tanh gates; best-known scan body) ----
            const float az0 = fmaf(h2, K[2][0], fmaf(h1, K[1][0], fmaf(h0, K[0][0], xz0)));
            const float az1 = fmaf(h2, K[2][1], fmaf(h1, K[1][1], fmaf(h0, K[0][1], xz1)));
            const float az2 = fmaf(h2, K[2][2], fmaf(h1, K[1][2], fmaf(h0, K[0][2], xz2)));
            const float ar0 = fmaf(h2, K[2][3], fmaf(h1, K[1][3], fmaf(h0, K[0][3], xr0)));
            const float ar1 = fmaf(h2, K[2][4], fmaf(h1, K[1][4], fmaf(h0, K[0][4], xr1)));
            const float ar2 = fmaf(h2, K[2][5], fmaf(h1, K[1][5], fmaf(h0, K[0][5], xr2)));
            const float hh0 = fmaf(h2, K[2][6], fmaf(h1, K[1][6], h0 * K[0][6]));
            const float hh1 = fmaf(h2, K[2][7], fmaf(h1, K[1][7], h0 * K[0][7]));
            const float hh2 = fmaf(h2, K[2][8], fmaf(h1, K[1][8], h0 * K[0][8]));

            const float tz0 = tanh_fast(az0);
            const float tz1 = tanh_fast(az1);
            const float tz2 = tanh_fast(az2);
            const float tr0 = tanh_fast(ar0);
            const float tr1 = tanh_fast(ar1);
            const float tr2 = tanh_fast(ar2);

            // g = m*(1-z) = halfm*(1 - tanh(a_z/2))
            const float g0 = fmaf(-halfm, tz0, halfm);
            const float g1 = fmaf(-halfm, tz1, halfm);
            const float g2 = fmaf(-halfm, tz2, halfm);

            // r = 0.5 + 0.5*tanh(a_r/2)
            const float r0 = fmaf(tr0, 0.5f, 0.5f);
            const float r1 = fmaf(tr1, 0.5f, 0.5f);
            const float r2 = fmaf(tr2, 0.5f, 0.5f);

            const float hc0 = tanh_fast(fmaf(r0, hh0, xh0));
            const float hc1 = tanh_fast(fmaf(r1, hh1, xh1));
            const float hc2 = tanh_fast(fmaf(r2, hh2, xh2));

            // h_new = h + g*(hc - h)
            h0 = fmaf(g0, hc0 - h0, h0);
            h1 = fmaf(g1, hc1 - h1, h1);
            h2 = fmaf(g2, hc2 - h2, h2);

            // out = halfm * dot(h_new, 2w) + db
            const float dot = fmaf(h2, w2, fmaf(h1, w1, h0 * w0));
            g_outT[(size_t)tc * Bb + b] = fmaf(halfm, dot, db);
        }
    }
}

// ---------------------------------------------------------------------------
// Transpose g_outT[t][b] -> out[b][t]
// ---------------------------------------------------------------------------
__global__ void transpose_kernel(float* __restrict__ out) {
    __shared__ float tile[32][33];
    const int bBase = blockIdx.x * 32;
    const int tBase = blockIdx.y * 32;

    tile[threadIdx.y][threadIdx.x] =
        g_outT[(size_t)(tBase + threadIdx.y) * Bb + (bBase + threadIdx.x)];
    __syncthreads();
    out[(size_t)(bBase + threadIdx.y) * Tt + (tBase + threadIdx.x)] =
        tile[threadIdx.x][threadIdx.y];
}

// ---------------------------------------------------------------------------
extern "C" void kernel_launch(void* const* d_in, const int* in_sizes, int n_in,
                              void* d_out, int out_size) {
    const float* x       = (const float*)d_in[0];  // (B,T,8)
    const float* kern    = (const float*)d_in[1];  // (8,9)
    const float* rk      = (const float*)d_in[2];  // (3,9)
    const float* bias_i  = (const float*)d_in[3];  // (9,)
    const float* bias_r  = (const float*)d_in[4];  // (9,)
    const float* dense_w = (const float*)d_in[5];  // (3,1)
    const float* dense_b = (const float*)d_in[6];  // (1,)
    float* out = (float*)d_out;                    // (B,T,1)

    (void)in_sizes; (void)n_in; (void)out_size;

    scan_kernel<<<Bb / 32, 32>>>(x, kern, rk, bias_i, bias_r, dense_w, dense_b);

    dim3 gC(Bb / 32, Tt / 32);
    transpose_kernel<<<gC, dim3(32, 32)>>>(out);
}